// round 16
// baseline (speedup 1.0000x reference)
#include <cuda_runtime.h>
#include <cuda_fp16.h>
#include <mma.h>
#include <math.h>

#define Nn   200000
#define Ee   3200000
#define Mm   100000
#define NEx  32
#define Hh   1024
#define NTt  11
#define Ll   8
#define EPSf 1e-5f

#define NPASS 17
#define NB2   196        // ceil(Nn / 1024) scan blocks
#define GB    3125       // gather grid: ceil(Nn/64) node-chunks
#define NBn   782        // ceil(Nn/256)
#define NHALF 100000     // Nn/2
#define HB    1563       // ceil(Mm/64) head blocks

using namespace nvcuda;

// ---------------- scratch (static device globals; no allocation) ----------------
__device__ __align__(128) float  g_x[(size_t)Nn * 32];   // residual stream (fp32)
__device__ __align__(128) float  g_h[(size_t)Nn * 32];   // biconv temp (h1)
__device__ __align__(128) __half g_po[(size_t)Nn * 16];  // x @ w_out   (fp16)
__device__ __align__(128) __half g_pb[(size_t)Nn * 16];  // x @ w_back  (fp16)
__device__ float g_s[Mm];
__device__ float g_statsA[NPASS * 64];  // per-pass: [0:32) sum, [32:64) sumsq
__device__ int   g_mx[NEx];
__device__ float g_sum[NEx];

// CSR scratch (zero-initialized at module load; re-zeroed per call after use)
__device__ int g_cnt_out[Nn], g_cnt_in[Nn];
__device__ int g_rout[Nn + 1], g_rin[Nn + 1];
__device__ int g_cur_out[Nn], g_cur_in[Nn];
__device__ int g_adj_out[Ee];
__device__ int g_adj_in[Ee];
__device__ int g_bsum[2][256];
__device__ int g_flagA[2][256];

__device__ __forceinline__ int fenc(float f) {
    int i = __float_as_int(f);
    return i >= 0 ? i : (i ^ 0x7FFFFFFF);
}
__device__ __forceinline__ float fdec(int i) {
    return __int_as_float(i >= 0 ? i : (i ^ 0x7FFFFFFF));
}

// ---------------- CSR build: histogram (+ per-call scratch init) ----------------
__global__ __launch_bounds__(256) void k_hist(const int* __restrict__ src,
                                              const int* __restrict__ dst)
{
    if (blockIdx.x == 0) {
        for (int t = threadIdx.x; t < NPASS * 64; t += blockDim.x) g_statsA[t] = 0.f;
        if (threadIdx.x < NEx) { g_mx[threadIdx.x] = (int)0x80000000; g_sum[threadIdx.x] = 0.f; }
    }
    int e = blockIdx.x * blockDim.x + threadIdx.x;
    if (e >= Ee) return;
    atomicAdd(&g_cnt_out[dst[e]], 1);
    atomicAdd(&g_cnt_in[src[e]], 1);
}

// ---------------- single-launch exclusive scan (decoupled lookback) ----------------
__global__ __launch_bounds__(256) void k_scanLB()
{
    int a = blockIdx.y;
    int bx = blockIdx.x;
    const int* cnt = a ? g_cnt_in : g_cnt_out;
    int* rptr = a ? g_rin : g_rout;
    int* cur  = a ? g_cur_in : g_cur_out;
    int base = bx * 1024 + threadIdx.x * 4;
    int c4[4], pre[4];
    int s = 0;
#pragma unroll
    for (int i = 0; i < 4; i++) {
        int id = base + i;
        c4[i] = (id < Nn) ? cnt[id] : 0;
        pre[i] = s;
        s += c4[i];
    }
    __shared__ int sh[256];
    sh[threadIdx.x] = s;
    __syncthreads();
    for (int off = 1; off < 256; off <<= 1) {
        int u = (threadIdx.x >= off) ? sh[threadIdx.x - off] : 0;
        __syncthreads();
        sh[threadIdx.x] += u;
        __syncthreads();
    }
    if (threadIdx.x == 0) {
        g_bsum[a][bx] = sh[255];
        __threadfence();
        atomicExch(&g_flagA[a][bx], 1);
        if (bx == 0) rptr[Nn] = Ee;
    }
    __shared__ int soff;
    if (threadIdx.x == 0) soff = 0;
    __syncthreads();
    int part = 0;
    for (int t = threadIdx.x; t < bx; t += 256) {
        while (atomicAdd(&g_flagA[a][t], 0) == 0) { }
        part += atomicAdd(&g_bsum[a][t], 0);
    }
    if (part) atomicAdd(&soff, part);
    __syncthreads();
    int toff = sh[threadIdx.x] - s + soff;
#pragma unroll
    for (int i = 0; i < 4; i++) {
        int id = base + i;
        if (id < Nn) { int p = toff + pre[i]; rptr[id] = p; cur[id] = p; }
    }
}

// ---------------- scatter + embed + first projection + scratch re-zero ----------------
__global__ __launch_bounds__(256) void k_scatter_embed(const int* __restrict__ src,
                                                       const int* __restrict__ dst,
                                                       const int* __restrict__ nodes,
                                                       const float* __restrict__ emb,
                                                       const float* __restrict__ w_o,
                                                       const float* __restrict__ w_b)
{
    __shared__ float semb[NTt * 32];
    __shared__ float swo[512], swb[512];
    bool nodeblk = (blockIdx.x < NBn);
    if (nodeblk) {
        for (int t = threadIdx.x; t < NTt * 32; t += blockDim.x) semb[t] = emb[t];
        for (int t = threadIdx.x; t < 512; t += blockDim.x) { swo[t] = w_o[t]; swb[t] = w_b[t]; }
        __syncthreads();
    }
    int gid = blockIdx.x * blockDim.x + threadIdx.x;
    if (gid < Ee) {
        int s = src[gid], d = dst[gid];
        g_adj_out[atomicAdd(&g_cur_out[d], 1)] = s;
        g_adj_in[atomicAdd(&g_cur_in[s], 1)] = d;
    }
    if (gid < 512) ((int*)g_flagA)[gid] = 0;
    if (gid < Nn) {
        g_cnt_out[gid] = 0;
        g_cnt_in[gid] = 0;
        int ty = nodes[gid];
        float tv[32];
#pragma unroll
        for (int c = 0; c < 32; c++) tv[c] = semb[ty * 32 + c];
        float o[16], b[16];
#pragma unroll
        for (int k = 0; k < 16; k++) { o[k] = 0.f; b[k] = 0.f; }
#pragma unroll 4
        for (int c = 0; c < 32; c++) {
            float tc = tv[c];
#pragma unroll
            for (int k = 0; k < 16; k++) {
                o[k] = fmaf(tc, swo[c * 16 + k], o[k]);
                b[k] = fmaf(tc, swb[c * 16 + k], b[k]);
            }
        }
        __half2 ho[8], hb[8];
#pragma unroll
        for (int k = 0; k < 8; k++) {
            ho[k] = __floats2half2_rn(o[2 * k], o[2 * k + 1]);
            hb[k] = __floats2half2_rn(b[2 * k], b[2 * k + 1]);
        }
        uint4* po = (uint4*)(g_po + (size_t)gid * 16);
        uint4* pb = (uint4*)(g_pb + (size_t)gid * 16);
        po[0] = *(uint4*)&ho[0]; po[1] = *(uint4*)&ho[4];
        pb[0] = *(uint4*)&hb[0]; pb[1] = *(uint4*)&hb[4];
    }
}

// ---------------- gather v4 (frozen R13): 2 neighbors/iter, HADD2 combine ----------
__global__ __launch_bounds__(256) void k_gather(int mode, int pass, int do_stats)
{
    int r = threadIdx.x & 1;                // 16B chunk
    int dir = (threadIdx.x >> 1) & 1;       // direction
    int nloc = threadIdx.x >> 2;            // 0..63
    const int* __restrict__ rp  = dir ? g_rin : g_rout;
    const int* __restrict__ adj = dir ? g_adj_in : g_adj_out;
    const uint4* __restrict__ tab = (const uint4*)(dir ? g_pb : g_po);

    float st_s[8], st_q[8];
#pragma unroll
    for (int k = 0; k < 8; k++) { st_s[k] = 0.f; st_q[k] = 0.f; }

    for (int n0b = blockIdx.x * 64; n0b < Nn; n0b += gridDim.x * 64) {
        int n = n0b + nloc;
        if (n < Nn) {
            int s = rp[n], e = rp[n + 1];
            float acc[8];
#pragma unroll
            for (int k = 0; k < 8; k++) acc[k] = 0.f;

            int j = s;
            int nb0 = (j < e) ? adj[j] : 0;
            int nb1 = (j + 1 < e) ? adj[j + 1] : -1;
            while (j < e) {
                int jn = j + 2;
                int p0 = (jn < e) ? adj[jn] : 0;            // prefetch next pair
                int p1 = (jn + 1 < e) ? adj[jn + 1] : -1;
                uint4 a = tab[(size_t)nb0 * 2 + r];
                uint4 b = make_uint4(0u, 0u, 0u, 0u);
                if (nb1 >= 0) b = tab[(size_t)nb1 * 2 + r];
                __half2 h0 = __hadd2(*(__half2*)&a.x, *(__half2*)&b.x);
                __half2 h1 = __hadd2(*(__half2*)&a.y, *(__half2*)&b.y);
                __half2 h2 = __hadd2(*(__half2*)&a.z, *(__half2*)&b.z);
                __half2 h3 = __hadd2(*(__half2*)&a.w, *(__half2*)&b.w);
                float2 f;
                f = __half22float2(h0); acc[0] += f.x; acc[1] += f.y;
                f = __half22float2(h1); acc[2] += f.x; acc[3] += f.y;
                f = __half22float2(h2); acc[4] += f.x; acc[5] += f.y;
                f = __half22float2(h3); acc[6] += f.x; acc[7] += f.y;
                nb0 = p0;
                nb1 = p1;
                j = jn;
            }

            float4 v0 = make_float4(acc[0], acc[1], acc[2], acc[3]);
            float4 v1 = make_float4(acc[4], acc[5], acc[6], acc[7]);
            float* dstp = ((mode == 1) ? g_h : g_x) + (size_t)n * 32 + dir * 16 + r * 8;
            if (mode == 2) {
                const float4* oldp = (const float4*)dstp;
                float4 o0 = oldp[0], o1 = oldp[1];
                v0.x += o0.x; v0.y += o0.y; v0.z += o0.z; v0.w += o0.w;
                v1.x += o1.x; v1.y += o1.y; v1.z += o1.z; v1.w += o1.w;
            }
            ((float4*)dstp)[0] = v0;
            ((float4*)dstp)[1] = v1;

            if (do_stats) {
                st_s[0] += v0.x; st_s[1] += v0.y; st_s[2] += v0.z; st_s[3] += v0.w;
                st_s[4] += v1.x; st_s[5] += v1.y; st_s[6] += v1.z; st_s[7] += v1.w;
                st_q[0] = fmaf(v0.x, v0.x, st_q[0]); st_q[1] = fmaf(v0.y, v0.y, st_q[1]);
                st_q[2] = fmaf(v0.z, v0.z, st_q[2]); st_q[3] = fmaf(v0.w, v0.w, st_q[3]);
                st_q[4] = fmaf(v1.x, v1.x, st_q[4]); st_q[5] = fmaf(v1.y, v1.y, st_q[5]);
                st_q[6] = fmaf(v1.z, v1.z, st_q[6]); st_q[7] = fmaf(v1.w, v1.w, st_q[7]);
            }
        }
    }
    if (!do_stats) return;

#pragma unroll
    for (int off = 4; off <= 16; off <<= 1) {
#pragma unroll
        for (int k = 0; k < 8; k++) {
            st_s[k] += __shfl_xor_sync(0xFFFFFFFFu, st_s[k], off);
            st_q[k] += __shfl_xor_sync(0xFFFFFFFFu, st_q[k], off);
        }
    }
    __shared__ float ss[64];
    if (threadIdx.x < 64) ss[threadIdx.x] = 0.f;
    __syncthreads();
    if ((threadIdx.x & 31) < 4) {
        int chb = dir * 16 + r * 8;
#pragma unroll
        for (int k = 0; k < 8; k++) {
            atomicAdd(&ss[chb + k], st_s[k]);
            atomicAdd(&ss[32 + chb + k], st_q[k]);
        }
    }
    __syncthreads();
    if (threadIdx.x < 64) atomicAdd(&g_statsA[pass * 64 + threadIdx.x], ss[threadIdx.x]);
}

// ---------------- BN+relu+projection: thread = (matrix, 2 nodes), fp32 FMA ----------
__global__ __launch_bounds__(256) void k_proj(int srcsel, int pass,
                                              const float* __restrict__ gamma,
                                              const float* __restrict__ beta,
                                              const float* __restrict__ w_o,
                                              const float* __restrict__ w_b)
{
    __shared__ float sA[32], sB[32];
    __shared__ float4 sw4[2][128];   // [m][c*4 + kq] = w[c][4kq..4kq+3]
    if (threadIdx.x < 32) {
        float m = g_statsA[pass * 64 + threadIdx.x] * (1.0f / Nn);
        float v = g_statsA[pass * 64 + 32 + threadIdx.x] * (1.0f / Nn) - m * m;
        float a = gamma[threadIdx.x] * rsqrtf(v + EPSf);
        sA[threadIdx.x] = a;
        sB[threadIdx.x] = fmaf(-m, a, beta[threadIdx.x]);
    }
    for (int t = threadIdx.x; t < 128; t += blockDim.x) {
        sw4[0][t] = ((const float4*)w_o)[t];
        sw4[1][t] = ((const float4*)w_b)[t];
    }
    __syncthreads();

    int gid = blockIdx.x * blockDim.x + threadIdx.x;   // 0 .. 2*NHALF-1
    int m = gid & 1, np = gid >> 1;
    if (np >= NHALF) return;
    int na = np, nb = np + NHALF;
    const float* xin = srcsel ? g_h : g_x;

    float tva[32], tvb[32];
    const float4* xra = (const float4*)(xin + (size_t)na * 32);
    const float4* xrb = (const float4*)(xin + (size_t)nb * 32);
#pragma unroll
    for (int qq = 0; qq < 8; qq++) {
        float4 va = xra[qq], vb = xrb[qq];
        float a0 = sA[qq * 4 + 0], a1 = sA[qq * 4 + 1], a2 = sA[qq * 4 + 2], a3 = sA[qq * 4 + 3];
        float b0 = sB[qq * 4 + 0], b1 = sB[qq * 4 + 1], b2 = sB[qq * 4 + 2], b3 = sB[qq * 4 + 3];
        tva[qq * 4 + 0] = fmaxf(fmaf(va.x, a0, b0), 0.f);
        tva[qq * 4 + 1] = fmaxf(fmaf(va.y, a1, b1), 0.f);
        tva[qq * 4 + 2] = fmaxf(fmaf(va.z, a2, b2), 0.f);
        tva[qq * 4 + 3] = fmaxf(fmaf(va.w, a3, b3), 0.f);
        tvb[qq * 4 + 0] = fmaxf(fmaf(vb.x, a0, b0), 0.f);
        tvb[qq * 4 + 1] = fmaxf(fmaf(vb.y, a1, b1), 0.f);
        tvb[qq * 4 + 2] = fmaxf(fmaf(vb.z, a2, b2), 0.f);
        tvb[qq * 4 + 3] = fmaxf(fmaf(vb.w, a3, b3), 0.f);
    }
    float oa[16], ob[16];
#pragma unroll
    for (int k = 0; k < 16; k++) { oa[k] = 0.f; ob[k] = 0.f; }
    const float4* w = sw4[m];
#pragma unroll 4
    for (int c = 0; c < 32; c++) {
        float ta = tva[c], tb = tvb[c];
#pragma unroll
        for (int kq = 0; kq < 4; kq++) {
            float4 wv = w[c * 4 + kq];
            oa[kq * 4 + 0] = fmaf(ta, wv.x, oa[kq * 4 + 0]);
            oa[kq * 4 + 1] = fmaf(ta, wv.y, oa[kq * 4 + 1]);
            oa[kq * 4 + 2] = fmaf(ta, wv.z, oa[kq * 4 + 2]);
            oa[kq * 4 + 3] = fmaf(ta, wv.w, oa[kq * 4 + 3]);
            ob[kq * 4 + 0] = fmaf(tb, wv.x, ob[kq * 4 + 0]);
            ob[kq * 4 + 1] = fmaf(tb, wv.y, ob[kq * 4 + 1]);
            ob[kq * 4 + 2] = fmaf(tb, wv.z, ob[kq * 4 + 2]);
            ob[kq * 4 + 3] = fmaf(tb, wv.w, ob[kq * 4 + 3]);
        }
    }
    __half* base = m ? g_pb : g_po;
    {
        __half2 hv[8];
#pragma unroll
        for (int k = 0; k < 8; k++) hv[k] = __floats2half2_rn(oa[2 * k], oa[2 * k + 1]);
        uint4* outp = (uint4*)(base + (size_t)na * 16);
        outp[0] = *(uint4*)&hv[0];
        outp[1] = *(uint4*)&hv[4];
    }
    {
        __half2 hv[8];
#pragma unroll
        for (int k = 0; k < 8; k++) hv[k] = __floats2half2_rn(ob[2 * k], ob[2 * k + 1]);
        uint4* outp = (uint4*)(base + (size_t)nb * 16);
        outp[0] = *(uint4*)&hv[0];
        outp[1] = *(uint4*)&hv[4];
    }
}

// ---------------- head MLP via wmma (HMMA, fp16 in / fp32 accum) --------------------
// Block: 128 threads (4 warps), 64 samples. Warp w owns 16-col slice of each 64-col
// j-tile; 4 row-tiles of 16. Lane keeps per-row partial (row fixed per lane).
__global__ __launch_bounds__(128) void k_head(const int* __restrict__ indices,
                                              const int* __restrict__ assign,
                                              const float* __restrict__ wh,
                                              const float* __restrict__ bh,
                                              const float* __restrict__ wo,
                                              const float* __restrict__ bo)
{
    __shared__ __half Xs[64 * 32];      // [row][c] ldm 32
    __shared__ __half Ws[32 * 64];      // [c][jj]  ldm 64
    __shared__ float  cbuf[4][16 * 16]; // per-warp fragment buffer
    __shared__ float  sbh[64], swoS[64];
    __shared__ float  sracc[64];
    __shared__ int    sseg[64];

    int tid = threadIdx.x;
    int warp = tid >> 5, lane = tid & 31;
    int row = tid >> 1, hf = tid & 1;   // each thread loads half a row of X
    int samp = blockIdx.x * 64 + row;

    if (tid < 64) sracc[tid] = 0.f;
    if (samp < Mm) {
        int idx = indices[samp];
        if (hf == 0) sseg[row] = assign[idx];
        const float4* p = (const float4*)(g_x + (size_t)idx * 32) + hf * 4;
#pragma unroll
        for (int q = 0; q < 4; q++) {
            float4 u = p[q];
            int off = row * 32 + hf * 16 + q * 4;
            Xs[off + 0] = __float2half(fmaxf(u.x, 0.f));
            Xs[off + 1] = __float2half(fmaxf(u.y, 0.f));
            Xs[off + 2] = __float2half(fmaxf(u.z, 0.f));
            Xs[off + 3] = __float2half(fmaxf(u.w, 0.f));
        }
    } else {
        if (hf == 0) sseg[row] = 0;
#pragma unroll
        for (int q = 0; q < 16; q++) Xs[row * 32 + hf * 16 + q] = __half(0.f);
    }
    __syncthreads();

    float racc[4] = {0.f, 0.f, 0.f, 0.f};
    int r16 = lane >> 1;                 // row within 16-tile
    int c0 = (lane & 1) * 8;             // col half within 16-slice

    for (int j0 = 0; j0 < Hh; j0 += 64) {
        for (int t = tid; t < 2048; t += 128) {
            int c = t >> 6, jj = t & 63;
            Ws[t] = __float2half(wh[c * Hh + j0 + jj]);
        }
        if (tid < 64) {
            sbh[tid] = bh[j0 + tid];
            swoS[tid] = wo[j0 + tid];
        }
        __syncthreads();

#pragma unroll
        for (int rt = 0; rt < 4; rt++) {
            wmma::fragment<wmma::accumulator, 16, 16, 16, float> fc;
            wmma::fill_fragment(fc, 0.f);
#pragma unroll
            for (int k0 = 0; k0 < 32; k0 += 16) {
                wmma::fragment<wmma::matrix_a, 16, 16, 16, __half, wmma::row_major> fa;
                wmma::fragment<wmma::matrix_b, 16, 16, 16, __half, wmma::row_major> fb;
                wmma::load_matrix_sync(fa, Xs + rt * 16 * 32 + k0, 32);
                wmma::load_matrix_sync(fb, Ws + k0 * 64 + warp * 16, 64);
                wmma::mma_sync(fc, fa, fb, fc);
            }
            wmma::store_matrix_sync(cbuf[warp], fc, 16, wmma::mem_row_major);
            __syncwarp();
            float part = 0.f;
#pragma unroll
            for (int c = 0; c < 8; c++) {
                int col = c0 + c;
                float h = cbuf[warp][r16 * 16 + col] + sbh[warp * 16 + col];
                part = fmaf(fmaxf(h, 0.f), swoS[warp * 16 + col], part);
            }
            racc[rt] += part;
            __syncwarp();
        }
        __syncthreads();
    }

    // combine lane pairs, then cross-warp into sracc
#pragma unroll
    for (int rt = 0; rt < 4; rt++) {
        racc[rt] += __shfl_xor_sync(0xFFFFFFFFu, racc[rt], 1);
        if ((lane & 1) == 0) atomicAdd(&sracc[rt * 16 + r16], racc[rt]);
    }
    __syncthreads();
    if (tid < 64) {
        int s2 = blockIdx.x * 64 + tid;
        if (s2 < Mm) {
            float s = sracc[tid] + bo[0];
            g_s[s2] = s;
            atomicMax(&g_mx[sseg[tid]], fenc(s));
        }
    }
}

__global__ __launch_bounds__(256) void k_lse(const int* __restrict__ indices,
                                             const int* __restrict__ assign)
{
    __shared__ float part[NEx];
    if (threadIdx.x < NEx) part[threadIdx.x] = 0.f;
    __syncthreads();
    int i = blockIdx.x * blockDim.x + threadIdx.x;
    if (i < Mm) {
        int seg = assign[indices[i]];
        float e = expf(g_s[i] - fdec(g_mx[seg]));
        atomicAdd(&part[seg], e);
    }
    __syncthreads();
    if (threadIdx.x < NEx && part[threadIdx.x] != 0.f)
        atomicAdd(&g_sum[threadIdx.x], part[threadIdx.x]);
}

__global__ __launch_bounds__(256) void k_out(const int* __restrict__ indices,
                                             const int* __restrict__ assign,
                                             float* __restrict__ out)
{
    int i = blockIdx.x * blockDim.x + threadIdx.x;
    if (i >= Mm) return;
    int seg = assign[indices[i]];
    out[i] = g_s[i] - fdec(g_mx[seg]) - logf(g_sum[seg]);
}

// ---------------- launch ----------------
extern "C" void kernel_launch(void* const* d_in, const int* in_sizes, int n_in,
                              void* d_out, int out_size)
{
    int o = n_in - 20;
    const int*   assignment = (const int*)d_in[o + 0];
    const int*   nodes      = (const int*)d_in[o + 1];
    const int*   src        = (const int*)d_in[o + 2];
    const int*   dst        = (const int*)d_in[o + 3];
    const int*   indices    = (const int*)d_in[o + 4];
    const float* emb        = (const float*)d_in[o + 5];
    const float* w0o        = (const float*)d_in[o + 6];
    const float* w0b        = (const float*)d_in[o + 7];
    const float* bn1g       = (const float*)d_in[o + 8];
    const float* bn1b       = (const float*)d_in[o + 9];
    const float* w1o        = (const float*)d_in[o + 10];
    const float* w1b        = (const float*)d_in[o + 11];
    const float* bn2g       = (const float*)d_in[o + 12];
    const float* bn2b       = (const float*)d_in[o + 13];
    const float* w2o        = (const float*)d_in[o + 14];
    const float* w2b        = (const float*)d_in[o + 15];
    const float* wh         = (const float*)d_in[o + 16];
    const float* bh         = (const float*)d_in[o + 17];
    const float* wo         = (const float*)d_in[o + 18];
    const float* bo         = (const float*)d_in[o + 19];
    float* out = (float*)d_out;

    const int eb = (Ee + 255) / 256;
    const int mb = (Mm + 255) / 256;
    const int pbgrid = (2 * NHALF + 255) / 256;

    k_hist<<<eb, 256>>>(src, dst);                                 // #1
    { dim3 g(NB2, 2); k_scanLB<<<g, 256>>>(); }                    // #2
    k_scatter_embed<<<eb, 256>>>(src, dst, nodes, emb, w0o, w0b);  // #3
    k_gather<<<GB, 256>>>(0, 0, 1);                                // #4 <- profiled launch
    for (int l = 0; l < Ll; l++) {
        k_proj<<<pbgrid, 256>>>(0, 2 * l, bn1g + l * 32, bn1b + l * 32,
                                w1o + l * 512, w1b + l * 512);
        k_gather<<<GB, 256>>>(1, 2 * l + 1, 1);
        k_proj<<<pbgrid, 256>>>(1, 2 * l + 1, bn2g + l * 32, bn2b + l * 32,
                                w2o + l * 512, w2b + l * 512);
        k_gather<<<GB, 256>>>(2, 2 * l + 2, l < Ll - 1 ? 1 : 0);
    }
    k_head<<<HB, 128>>>(indices, assignment, wh, bh, wo, bo);
    k_lse<<<mb, 256>>>(indices, assignment);
    k_out<<<mb, 256>>>(indices, assignment, out);
}

// round 17
// speedup vs baseline: 1.0228x; 1.0228x over previous
#include <cuda_runtime.h>
#include <cuda_fp16.h>
#include <math.h>

#define Nn   200000
#define Ee   3200000
#define Mm   100000
#define MH   50000       // Mm/2
#define NEx  32
#define Hh   1024
#define NTt  11
#define Ll   8
#define EPSf 1e-5f

#define NPASS 17
#define NB2   196        // ceil(Nn / 1024) scan blocks
#define GBUILD 392       // 2*NB2 persistent build blocks (co-resident by launch_bounds)
#define GB    3125       // gather grid: ceil(Nn/64) node-chunks
#define NHALF 100000     // Nn/2

// ---------------- scratch (static device globals; no allocation) ----------------
__device__ __align__(128) float  g_x[(size_t)Nn * 32];   // residual stream (fp32)
__device__ __align__(128) float  g_h[(size_t)Nn * 32];   // biconv temp (h1)
__device__ __align__(128) __half g_po[(size_t)Nn * 16];  // x @ w_out   (fp16)
__device__ __align__(128) __half g_pb[(size_t)Nn * 16];  // x @ w_back  (fp16)
__device__ float g_s[Mm];
__device__ float g_statsA[NPASS * 64];  // per-pass: [0:32) sum, [32:64) sumsq
__device__ int   g_mx[NEx];
__device__ float g_sum[NEx];

// CSR scratch (zero-initialized at module load; re-zeroed per call after use)
__device__ int g_cnt_out[Nn], g_cnt_in[Nn];
__device__ int g_rout[Nn + 1], g_rin[Nn + 1];
__device__ int g_cur_out[Nn], g_cur_in[Nn];
__device__ int g_adj_out[Ee];
__device__ int g_adj_in[Ee];
__device__ int g_bsum[2][256];
__device__ int g_flagA[2][256];   // lookback flags (reset by k_out for next call)
__device__ int g_gbar[2];         // device barrier counters (reset by k_out)

__device__ __forceinline__ int fenc(float f) {
    int i = __float_as_int(f);
    return i >= 0 ? i : (i ^ 0x7FFFFFFF);
}
__device__ __forceinline__ float fdec(int i) {
    return __int_as_float(i >= 0 ? i : (i ^ 0x7FFFFFFF));
}

__device__ __forceinline__ void gbarrier(int* ctr) {
    __syncthreads();
    if (threadIdx.x == 0) {
        __threadfence();
        atomicAdd(ctr, 1);
        while (atomicAdd(ctr, 0) < GBUILD) { }
    }
    __syncthreads();
}

// ---------------- fused CSR build: hist -> scan -> scatter+embed ----------------
// 392 blocks, guaranteed co-resident (launch_bounds(256,3) -> 444-block capacity),
// so the two device-wide spin barriers are deadlock-free.
__global__ __launch_bounds__(256, 3) void k_build(const int* __restrict__ src,
                                                  const int* __restrict__ dst,
                                                  const int* __restrict__ nodes,
                                                  const float* __restrict__ emb,
                                                  const float* __restrict__ w_o,
                                                  const float* __restrict__ w_b)
{
    int tid = threadIdx.x;
    int blk = blockIdx.x;
    int gthread = blk * 256 + tid;
    const int nth = GBUILD * 256;

    __shared__ int sh[256];
    __shared__ int soff;
    __shared__ float semb[NTt * 32];
    __shared__ float swo[512], swb[512];

    // per-call scratch init (block 0)
    if (blk == 0) {
        for (int t = tid; t < NPASS * 64; t += 256) g_statsA[t] = 0.f;
        if (tid < NEx) { g_mx[tid] = (int)0x80000000; g_sum[tid] = 0.f; }
    }

    // ---- phase 1: degree histogram, 4 edges/iter (int4 loads, 8 REDs in flight) ----
    const int4* s4 = (const int4*)src;
    const int4* d4 = (const int4*)dst;
    for (int i = gthread; i < Ee / 4; i += nth) {
        int4 s = s4[i], d = d4[i];
        atomicAdd(&g_cnt_out[d.x], 1); atomicAdd(&g_cnt_in[s.x], 1);
        atomicAdd(&g_cnt_out[d.y], 1); atomicAdd(&g_cnt_in[s.y], 1);
        atomicAdd(&g_cnt_out[d.z], 1); atomicAdd(&g_cnt_in[s.z], 1);
        atomicAdd(&g_cnt_out[d.w], 1); atomicAdd(&g_cnt_in[s.w], 1);
    }
    gbarrier(&g_gbar[0]);

    // ---- phase 2: decoupled-lookback exclusive scan (both directions) ----
    {
        int a = (blk >= NB2) ? 1 : 0;
        int bx = a ? (blk - NB2) : blk;
        const int* cnt = a ? g_cnt_in : g_cnt_out;
        int* rptr = a ? g_rin : g_rout;
        int* cur  = a ? g_cur_in : g_cur_out;
        int base = bx * 1024 + tid * 4;
        int c4[4], pre[4];
        int s = 0;
#pragma unroll
        for (int i = 0; i < 4; i++) {
            int id = base + i;
            c4[i] = (id < Nn) ? cnt[id] : 0;
            pre[i] = s;
            s += c4[i];
        }
        sh[tid] = s;
        __syncthreads();
        for (int off = 1; off < 256; off <<= 1) {
            int u = (tid >= off) ? sh[tid - off] : 0;
            __syncthreads();
            sh[tid] += u;
            __syncthreads();
        }
        if (tid == 0) {
            g_bsum[a][bx] = sh[255];
            __threadfence();
            atomicExch(&g_flagA[a][bx], 1);
            if (bx == 0) rptr[Nn] = Ee;
            soff = 0;
        }
        __syncthreads();
        int part = 0;
        for (int t = tid; t < bx; t += 256) {
            while (atomicAdd(&g_flagA[a][t], 0) == 0) { }
            part += atomicAdd(&g_bsum[a][t], 0);
        }
        if (part) atomicAdd(&soff, part);
        __syncthreads();
        int toff = sh[tid] - s + soff;
#pragma unroll
        for (int i = 0; i < 4; i++) {
            int id = base + i;
            if (id < Nn) { int p = toff + pre[i]; rptr[id] = p; cur[id] = p; }
        }
    }
    gbarrier(&g_gbar[1]);

    // ---- phase 3: scatter (2 edges/iter) + embed + counter re-zero ----
    for (int t = tid; t < NTt * 32; t += 256) semb[t] = emb[t];
    for (int t = tid; t < 512; t += 256) { swo[t] = w_o[t]; swb[t] = w_b[t]; }
    __syncthreads();

    const int2* s2 = (const int2*)src;
    const int2* d2 = (const int2*)dst;
    for (int i = gthread; i < Ee / 2; i += nth) {
        int2 s = s2[i], d = d2[i];
        g_adj_out[atomicAdd(&g_cur_out[d.x], 1)] = s.x;
        g_adj_in [atomicAdd(&g_cur_in [s.x], 1)] = d.x;
        g_adj_out[atomicAdd(&g_cur_out[d.y], 1)] = s.y;
        g_adj_in [atomicAdd(&g_cur_in [s.y], 1)] = d.y;
    }
    for (int n = gthread; n < Nn; n += nth) {
        g_cnt_out[n] = 0;   // leave zeroed for next call
        g_cnt_in[n] = 0;
        int ty = nodes[n];
        float tv[32];
#pragma unroll
        for (int c = 0; c < 32; c++) tv[c] = semb[ty * 32 + c];
        float o[16], b[16];
#pragma unroll
        for (int k = 0; k < 16; k++) { o[k] = 0.f; b[k] = 0.f; }
#pragma unroll 4
        for (int c = 0; c < 32; c++) {
            float tc = tv[c];
#pragma unroll
            for (int k = 0; k < 16; k++) {
                o[k] = fmaf(tc, swo[c * 16 + k], o[k]);
                b[k] = fmaf(tc, swb[c * 16 + k], b[k]);
            }
        }
        __half2 ho[8], hb[8];
#pragma unroll
        for (int k = 0; k < 8; k++) {
            ho[k] = __floats2half2_rn(o[2 * k], o[2 * k + 1]);
            hb[k] = __floats2half2_rn(b[2 * k], b[2 * k + 1]);
        }
        uint4* po = (uint4*)(g_po + (size_t)n * 16);
        uint4* pb = (uint4*)(g_pb + (size_t)n * 16);
        po[0] = *(uint4*)&ho[0]; po[1] = *(uint4*)&ho[4];
        pb[0] = *(uint4*)&hb[0]; pb[1] = *(uint4*)&hb[4];
    }
}

// ---------------- gather v4 (frozen R13): 2 neighbors/iter, HADD2 combine ----------
__global__ __launch_bounds__(256) void k_gather(int mode, int pass, int do_stats)
{
    int r = threadIdx.x & 1;                // 16B chunk
    int dir = (threadIdx.x >> 1) & 1;       // direction
    int nloc = threadIdx.x >> 2;            // 0..63
    const int* __restrict__ rp  = dir ? g_rin : g_rout;
    const int* __restrict__ adj = dir ? g_adj_in : g_adj_out;
    const uint4* __restrict__ tab = (const uint4*)(dir ? g_pb : g_po);

    float st_s[8], st_q[8];
#pragma unroll
    for (int k = 0; k < 8; k++) { st_s[k] = 0.f; st_q[k] = 0.f; }

    for (int n0b = blockIdx.x * 64; n0b < Nn; n0b += gridDim.x * 64) {
        int n = n0b + nloc;
        if (n < Nn) {
            int s = rp[n], e = rp[n + 1];
            float acc[8];
#pragma unroll
            for (int k = 0; k < 8; k++) acc[k] = 0.f;

            int j = s;
            int nb0 = (j < e) ? adj[j] : 0;
            int nb1 = (j + 1 < e) ? adj[j + 1] : -1;
            while (j < e) {
                int jn = j + 2;
                int p0 = (jn < e) ? adj[jn] : 0;            // prefetch next pair
                int p1 = (jn + 1 < e) ? adj[jn + 1] : -1;
                uint4 a = tab[(size_t)nb0 * 2 + r];
                uint4 b = make_uint4(0u, 0u, 0u, 0u);
                if (nb1 >= 0) b = tab[(size_t)nb1 * 2 + r];
                __half2 h0 = __hadd2(*(__half2*)&a.x, *(__half2*)&b.x);
                __half2 h1 = __hadd2(*(__half2*)&a.y, *(__half2*)&b.y);
                __half2 h2 = __hadd2(*(__half2*)&a.z, *(__half2*)&b.z);
                __half2 h3 = __hadd2(*(__half2*)&a.w, *(__half2*)&b.w);
                float2 f;
                f = __half22float2(h0); acc[0] += f.x; acc[1] += f.y;
                f = __half22float2(h1); acc[2] += f.x; acc[3] += f.y;
                f = __half22float2(h2); acc[4] += f.x; acc[5] += f.y;
                f = __half22float2(h3); acc[6] += f.x; acc[7] += f.y;
                nb0 = p0;
                nb1 = p1;
                j = jn;
            }

            float4 v0 = make_float4(acc[0], acc[1], acc[2], acc[3]);
            float4 v1 = make_float4(acc[4], acc[5], acc[6], acc[7]);
            float* dstp = ((mode == 1) ? g_h : g_x) + (size_t)n * 32 + dir * 16 + r * 8;
            if (mode == 2) {
                const float4* oldp = (const float4*)dstp;
                float4 o0 = oldp[0], o1 = oldp[1];
                v0.x += o0.x; v0.y += o0.y; v0.z += o0.z; v0.w += o0.w;
                v1.x += o1.x; v1.y += o1.y; v1.z += o1.z; v1.w += o1.w;
            }
            ((float4*)dstp)[0] = v0;
            ((float4*)dstp)[1] = v1;

            if (do_stats) {
                st_s[0] += v0.x; st_s[1] += v0.y; st_s[2] += v0.z; st_s[3] += v0.w;
                st_s[4] += v1.x; st_s[5] += v1.y; st_s[6] += v1.z; st_s[7] += v1.w;
                st_q[0] = fmaf(v0.x, v0.x, st_q[0]); st_q[1] = fmaf(v0.y, v0.y, st_q[1]);
                st_q[2] = fmaf(v0.z, v0.z, st_q[2]); st_q[3] = fmaf(v0.w, v0.w, st_q[3]);
                st_q[4] = fmaf(v1.x, v1.x, st_q[4]); st_q[5] = fmaf(v1.y, v1.y, st_q[5]);
                st_q[6] = fmaf(v1.z, v1.z, st_q[6]); st_q[7] = fmaf(v1.w, v1.w, st_q[7]);
            }
        }
    }
    if (!do_stats) return;

#pragma unroll
    for (int off = 4; off <= 16; off <<= 1) {
#pragma unroll
        for (int k = 0; k < 8; k++) {
            st_s[k] += __shfl_xor_sync(0xFFFFFFFFu, st_s[k], off);
            st_q[k] += __shfl_xor_sync(0xFFFFFFFFu, st_q[k], off);
        }
    }
    __shared__ float ss[64];
    if (threadIdx.x < 64) ss[threadIdx.x] = 0.f;
    __syncthreads();
    if ((threadIdx.x & 31) < 4) {
        int chb = dir * 16 + r * 8;
#pragma unroll
        for (int k = 0; k < 8; k++) {
            atomicAdd(&ss[chb + k], st_s[k]);
            atomicAdd(&ss[32 + chb + k], st_q[k]);
        }
    }
    __syncthreads();
    if (threadIdx.x < 64) atomicAdd(&g_statsA[pass * 64 + threadIdx.x], ss[threadIdx.x]);
}

// ---------------- BN+relu+projection: thread = (matrix, 2 nodes), fp32 FMA ----------
__global__ __launch_bounds__(256) void k_proj(int srcsel, int pass,
                                              const float* __restrict__ gamma,
                                              const float* __restrict__ beta,
                                              const float* __restrict__ w_o,
                                              const float* __restrict__ w_b)
{
    __shared__ float sA[32], sB[32];
    __shared__ float4 sw4[2][128];   // [m][c*4 + kq] = w[c][4kq..4kq+3]
    if (threadIdx.x < 32) {
        float m = g_statsA[pass * 64 + threadIdx.x] * (1.0f / Nn);
        float v = g_statsA[pass * 64 + 32 + threadIdx.x] * (1.0f / Nn) - m * m;
        float a = gamma[threadIdx.x] * rsqrtf(v + EPSf);
        sA[threadIdx.x] = a;
        sB[threadIdx.x] = fmaf(-m, a, beta[threadIdx.x]);
    }
    for (int t = threadIdx.x; t < 128; t += blockDim.x) {
        sw4[0][t] = ((const float4*)w_o)[t];
        sw4[1][t] = ((const float4*)w_b)[t];
    }
    __syncthreads();

    int gid = blockIdx.x * blockDim.x + threadIdx.x;   // 0 .. 2*NHALF-1
    int m = gid & 1, np = gid >> 1;
    if (np >= NHALF) return;
    int na = np, nb = np + NHALF;
    const float* xin = srcsel ? g_h : g_x;

    float tva[32], tvb[32];
    const float4* xra = (const float4*)(xin + (size_t)na * 32);
    const float4* xrb = (const float4*)(xin + (size_t)nb * 32);
#pragma unroll
    for (int qq = 0; qq < 8; qq++) {
        float4 va = xra[qq], vb = xrb[qq];
        float a0 = sA[qq * 4 + 0], a1 = sA[qq * 4 + 1], a2 = sA[qq * 4 + 2], a3 = sA[qq * 4 + 3];
        float b0 = sB[qq * 4 + 0], b1 = sB[qq * 4 + 1], b2 = sB[qq * 4 + 2], b3 = sB[qq * 4 + 3];
        tva[qq * 4 + 0] = fmaxf(fmaf(va.x, a0, b0), 0.f);
        tva[qq * 4 + 1] = fmaxf(fmaf(va.y, a1, b1), 0.f);
        tva[qq * 4 + 2] = fmaxf(fmaf(va.z, a2, b2), 0.f);
        tva[qq * 4 + 3] = fmaxf(fmaf(va.w, a3, b3), 0.f);
        tvb[qq * 4 + 0] = fmaxf(fmaf(vb.x, a0, b0), 0.f);
        tvb[qq * 4 + 1] = fmaxf(fmaf(vb.y, a1, b1), 0.f);
        tvb[qq * 4 + 2] = fmaxf(fmaf(vb.z, a2, b2), 0.f);
        tvb[qq * 4 + 3] = fmaxf(fmaf(vb.w, a3, b3), 0.f);
    }
    float oa[16], ob[16];
#pragma unroll
    for (int k = 0; k < 16; k++) { oa[k] = 0.f; ob[k] = 0.f; }
    const float4* w = sw4[m];
#pragma unroll 4
    for (int c = 0; c < 32; c++) {
        float ta = tva[c], tb = tvb[c];
#pragma unroll
        for (int kq = 0; kq < 4; kq++) {
            float4 wv = w[c * 4 + kq];
            oa[kq * 4 + 0] = fmaf(ta, wv.x, oa[kq * 4 + 0]);
            oa[kq * 4 + 1] = fmaf(ta, wv.y, oa[kq * 4 + 1]);
            oa[kq * 4 + 2] = fmaf(ta, wv.z, oa[kq * 4 + 2]);
            oa[kq * 4 + 3] = fmaf(ta, wv.w, oa[kq * 4 + 3]);
            ob[kq * 4 + 0] = fmaf(tb, wv.x, ob[kq * 4 + 0]);
            ob[kq * 4 + 1] = fmaf(tb, wv.y, ob[kq * 4 + 1]);
            ob[kq * 4 + 2] = fmaf(tb, wv.z, ob[kq * 4 + 2]);
            ob[kq * 4 + 3] = fmaf(tb, wv.w, ob[kq * 4 + 3]);
        }
    }
    __half* base = m ? g_pb : g_po;
    {
        __half2 hv[8];
#pragma unroll
        for (int k = 0; k < 8; k++) hv[k] = __floats2half2_rn(oa[2 * k], oa[2 * k + 1]);
        uint4* outp = (uint4*)(base + (size_t)na * 16);
        outp[0] = *(uint4*)&hv[0];
        outp[1] = *(uint4*)&hv[4];
    }
    {
        __half2 hv[8];
#pragma unroll
        for (int k = 0; k < 8; k++) hv[k] = __floats2half2_rn(ob[2 * k], ob[2 * k + 1]);
        uint4* outp = (uint4*)(base + (size_t)nb * 16);
        outp[0] = *(uint4*)&hv[0];
        outp[1] = *(uint4*)&hv[4];
    }
}

// ---------------- head MLP (R15 scalar): thread = 2 samples sharing weight loads ----
__global__ __launch_bounds__(128) void k_head(const int* __restrict__ indices,
                                              const int* __restrict__ assign,
                                              const float* __restrict__ wh,
                                              const float* __restrict__ bh,
                                              const float* __restrict__ wo,
                                              const float* __restrict__ bo)
{
    __shared__ float4 ws4[32 * 16];   // [c][jj/4] for a 64-wide jj tile
    __shared__ float sbh[64], swo2[64];
    int ia = blockIdx.x * blockDim.x + threadIdx.x;   // sample A: 0..MH-1
    int ib = ia + MH;                                  // sample B
    bool va = (ia < MH);
    float ra[32], rb[32];
    int sega = 0, segb = 0;
    if (va) {
        int idxa = indices[ia], idxb = indices[ib];
        sega = assign[idxa];
        segb = assign[idxb];
        const float4* pa = (const float4*)(g_x + (size_t)idxa * 32);
        const float4* pb = (const float4*)(g_x + (size_t)idxb * 32);
#pragma unroll
        for (int qq = 0; qq < 8; qq++) {
            float4 u = pa[qq], v = pb[qq];
            ra[qq * 4 + 0] = fmaxf(u.x, 0.f); ra[qq * 4 + 1] = fmaxf(u.y, 0.f);
            ra[qq * 4 + 2] = fmaxf(u.z, 0.f); ra[qq * 4 + 3] = fmaxf(u.w, 0.f);
            rb[qq * 4 + 0] = fmaxf(v.x, 0.f); rb[qq * 4 + 1] = fmaxf(v.y, 0.f);
            rb[qq * 4 + 2] = fmaxf(v.z, 0.f); rb[qq * 4 + 3] = fmaxf(v.w, 0.f);
        }
    } else {
#pragma unroll
        for (int c = 0; c < 32; c++) { ra[c] = 0.f; rb[c] = 0.f; }
    }
    float acca = 0.f, accb = 0.f;
    for (int j0 = 0; j0 < Hh; j0 += 64) {
        __syncthreads();
        for (int t = threadIdx.x; t < 32 * 16; t += blockDim.x) {
            int c = t >> 4, jq = t & 15;
            ws4[t] = *(const float4*)(wh + c * Hh + j0 + jq * 4);
        }
        if (threadIdx.x < 64) {
            sbh[threadIdx.x] = bh[j0 + threadIdx.x];
            swo2[threadIdx.x] = wo[j0 + threadIdx.x];
        }
        __syncthreads();
#pragma unroll 2
        for (int jq = 0; jq < 16; jq++) {
            float4 za = make_float4(sbh[jq * 4 + 0], sbh[jq * 4 + 1],
                                    sbh[jq * 4 + 2], sbh[jq * 4 + 3]);
            float4 zb = za;
#pragma unroll
            for (int c = 0; c < 32; c++) {
                float4 w = ws4[c * 16 + jq];
                float rca = ra[c], rcb = rb[c];
                za.x = fmaf(rca, w.x, za.x); za.y = fmaf(rca, w.y, za.y);
                za.z = fmaf(rca, w.z, za.z); za.w = fmaf(rca, w.w, za.w);
                zb.x = fmaf(rcb, w.x, zb.x); zb.y = fmaf(rcb, w.y, zb.y);
                zb.z = fmaf(rcb, w.z, zb.z); zb.w = fmaf(rcb, w.w, zb.w);
            }
            float w0 = swo2[jq * 4 + 0], w1 = swo2[jq * 4 + 1];
            float w2 = swo2[jq * 4 + 2], w3 = swo2[jq * 4 + 3];
            acca = fmaf(fmaxf(za.x, 0.f), w0, acca);
            acca = fmaf(fmaxf(za.y, 0.f), w1, acca);
            acca = fmaf(fmaxf(za.z, 0.f), w2, acca);
            acca = fmaf(fmaxf(za.w, 0.f), w3, acca);
            accb = fmaf(fmaxf(zb.x, 0.f), w0, accb);
            accb = fmaf(fmaxf(zb.y, 0.f), w1, accb);
            accb = fmaf(fmaxf(zb.z, 0.f), w2, accb);
            accb = fmaf(fmaxf(zb.w, 0.f), w3, accb);
        }
    }
    if (va) {
        float b0 = bo[0];
        float sa = acca + b0, sb = accb + b0;
        g_s[ia] = sa;
        g_s[ib] = sb;
        atomicMax(&g_mx[sega], fenc(sa));
        atomicMax(&g_mx[segb], fenc(sb));
    }
}

__global__ __launch_bounds__(256) void k_lse(const int* __restrict__ indices,
                                             const int* __restrict__ assign)
{
    __shared__ float part[NEx];
    if (threadIdx.x < NEx) part[threadIdx.x] = 0.f;
    __syncthreads();
    int i = blockIdx.x * blockDim.x + threadIdx.x;
    if (i < Mm) {
        int seg = assign[indices[i]];
        float e = expf(g_s[i] - fdec(g_mx[seg]));
        atomicAdd(&part[seg], e);
    }
    __syncthreads();
    if (threadIdx.x < NEx && part[threadIdx.x] != 0.f)
        atomicAdd(&g_sum[threadIdx.x], part[threadIdx.x]);
}

__global__ __launch_bounds__(256) void k_out(const int* __restrict__ indices,
                                             const int* __restrict__ assign,
                                             float* __restrict__ out)
{
    // reset lookback flags + build barriers for the next call (build long finished)
    if (blockIdx.x == 0) {
        for (int t = threadIdx.x; t < 512; t += 256) ((int*)g_flagA)[t] = 0;
        if (threadIdx.x < 2) g_gbar[threadIdx.x] = 0;
    }
    int i = blockIdx.x * blockDim.x + threadIdx.x;
    if (i >= Mm) return;
    int seg = assign[indices[i]];
    out[i] = g_s[i] - fdec(g_mx[seg]) - logf(g_sum[seg]);
}

// ---------------- launch ----------------
extern "C" void kernel_launch(void* const* d_in, const int* in_sizes, int n_in,
                              void* d_out, int out_size)
{
    int o = n_in - 20;
    const int*   assignment = (const int*)d_in[o + 0];
    const int*   nodes      = (const int*)d_in[o + 1];
    const int*   src        = (const int*)d_in[o + 2];
    const int*   dst        = (const int*)d_in[o + 3];
    const int*   indices    = (const int*)d_in[o + 4];
    const float* emb        = (const float*)d_in[o + 5];
    const float* w0o        = (const float*)d_in[o + 6];
    const float* w0b        = (const float*)d_in[o + 7];
    const float* bn1g       = (const float*)d_in[o + 8];
    const float* bn1b       = (const float*)d_in[o + 9];
    const float* w1o        = (const float*)d_in[o + 10];
    const float* w1b        = (const float*)d_in[o + 11];
    const float* bn2g       = (const float*)d_in[o + 12];
    const float* bn2b       = (const float*)d_in[o + 13];
    const float* w2o        = (const float*)d_in[o + 14];
    const float* w2b        = (const float*)d_in[o + 15];
    const float* wh         = (const float*)d_in[o + 16];
    const float* bh         = (const float*)d_in[o + 17];
    const float* wo         = (const float*)d_in[o + 18];
    const float* bo         = (const float*)d_in[o + 19];
    float* out = (float*)d_out;

    const int mb = (Mm + 255) / 256;
    const int hb = (MH + 127) / 128;
    const int pbgrid = (2 * NHALF + 255) / 256;

    k_build<<<GBUILD, 256>>>(src, dst, nodes, emb, w0o, w0b);  // #1 (hist+scan+scatter)
    k_gather<<<GB, 256>>>(0, 0, 1);                            // #2
    for (int l = 0; l < Ll; l++) {
        k_proj<<<pbgrid, 256>>>(0, 2 * l, bn1g + l * 32, bn1b + l * 32,
                                w1o + l * 512, w1b + l * 512);
        k_gather<<<GB, 256>>>(1, 2 * l + 1, 1);                // l=0: #4 <- profiled
        k_proj<<<pbgrid, 256>>>(1, 2 * l + 1, bn2g + l * 32, bn2b + l * 32,
                                w2o + l * 512, w2b + l * 512);
        k_gather<<<GB, 256>>>(2, 2 * l + 2, l < Ll - 1 ? 1 : 0);
    }
    k_head<<<hb, 128>>>(indices, assignment, wh, bh, wo, bo);
    k_lse<<<mb, 256>>>(indices, assignment);
    k_out<<<mb, 256>>>(indices, assignment, out);
}